// round 1
// baseline (speedup 1.0000x reference)
#include <cuda_runtime.h>
#include <cstdint>

#define N_ROWS 4096
#define DIM    512
#define VWORDS 50000
#define KNN    10

#define TM 64
#define TN 64
#define KC 32
#define VTILES ((VWORDS + TN - 1) / TN)   /* 782 */
#define RTILES (N_ROWS / TM)              /* 64  */

// Scratch (no allocations allowed in kernel_launch)
__device__ float g_w2[VWORDS];
__device__ float g_st[N_ROWS];
__device__ int   g_tgt[N_ROWS];
__device__ int   g_rowlist[N_ROWS];
__device__ int   g_counts[N_ROWS];
__device__ int   g_nm;

// ---------------------------------------------------------------------------
// K0: zero counters
__global__ void k_zero() {
    int i = blockIdx.x * blockDim.x + threadIdx.x;
    if (i < N_ROWS) g_counts[i] = 0;
    if (i == 0) g_nm = 0;
}

// ---------------------------------------------------------------------------
// K1: w2[v] = ||w_v||^2
__global__ void k_w2(const float* __restrict__ W) {
    int v = blockIdx.x;
    const float4* w = reinterpret_cast<const float4*>(W + (size_t)v * DIM);
    float4 x = w[threadIdx.x];  // 128 threads * 4 = 512
    float s = x.x * x.x + x.y * x.y + x.z * x.z + x.w * x.w;
#pragma unroll
    for (int o = 16; o; o >>= 1) s += __shfl_down_sync(0xffffffffu, s, o);
    __shared__ float red[4];
    if ((threadIdx.x & 31) == 0) red[threadIdx.x >> 5] = s;
    __syncthreads();
    if (threadIdx.x == 0) g_w2[v] = red[0] + red[1] + red[2] + red[3];
}

// ---------------------------------------------------------------------------
// K2: compact masked rows; per masked row compute s_t = w2[t] - 2 * x.w_t
__global__ void k_target(const float* __restrict__ X, const long long* __restrict__ tgt,
                         const int* __restrict__ mask, const float* __restrict__ W) {
    int n = blockIdx.x;
    if (mask[n] == 0) return;
    int t = (int)tgt[n];
    const float4* x = reinterpret_cast<const float4*>(X + (size_t)n * DIM);
    const float4* w = reinterpret_cast<const float4*>(W + (size_t)t * DIM);
    float4 a = x[threadIdx.x];
    float4 b = w[threadIdx.x];
    float s = a.x * b.x + a.y * b.y + a.z * b.z + a.w * b.w;
#pragma unroll
    for (int o = 16; o; o >>= 1) s += __shfl_down_sync(0xffffffffu, s, o);
    __shared__ float red[4];
    if ((threadIdx.x & 31) == 0) red[threadIdx.x >> 5] = s;
    __syncthreads();
    if (threadIdx.x == 0) {
        float dot = red[0] + red[1] + red[2] + red[3];
        int i = atomicAdd(&g_nm, 1);
        g_rowlist[i] = n;
        g_st[i] = g_w2[t] - 2.0f * dot;
        g_tgt[i] = t;
    }
}

// ---------------------------------------------------------------------------
// K3: tiled GEMM-compare. For each masked row i and word v, compute
// s = w2[v] - 2*dot(x,w_v) and count (s < s_t) || (s == s_t && v < t), v != t.
// blockIdx.x = row tile (so consecutive blocks share the same W tile in L2),
// blockIdx.y = word tile.
__global__ __launch_bounds__(256) void k_count(const float* __restrict__ X,
                                               const float* __restrict__ W) {
    const int nm = g_nm;
    const int row0 = blockIdx.x * TM;
    if (row0 >= nm) return;
    const int col0 = blockIdx.y * TN;

    __shared__ float Xs[TM][KC];   // row-major
    __shared__ float Ws[KC][TN];   // k-major, col4 XOR-swizzled by (k>>2)
    __shared__ float st_s[TM];
    __shared__ float w2s[TN];
    __shared__ int   tgt_s[TM];
    __shared__ int   rowg_s[TM];
    __shared__ int   vrow_s[TM];
    __shared__ int   cnt_s[TM];

    const int tid = threadIdx.x;
    const int tx = tid & 15;
    const int ty = tid >> 4;

    // Preamble: per-row / per-col metadata
    for (int i = tid; i < TM; i += 256) {
        int gi = row0 + i;
        int valid = gi < nm;
        rowg_s[i] = valid ? g_rowlist[gi] : 0;
        st_s[i]   = valid ? g_st[gi] : 0.0f;
        tgt_s[i]  = valid ? g_tgt[gi] : -1;
        vrow_s[i] = valid;
        cnt_s[i]  = 0;
    }
    for (int i = tid; i < TN; i += 256) {
        int v = col0 + i;
        w2s[i] = (v < VWORDS) ? g_w2[v] : 0.0f;
    }
    __syncthreads();

    float acc[4][4];
#pragma unroll
    for (int i = 0; i < 4; i++)
#pragma unroll
        for (int j = 0; j < 4; j++) acc[i][j] = 0.0f;

    for (int kb = 0; kb < DIM; kb += KC) {
        // X tile: 64 rows x 32 k = 512 float4, 2 per thread
#pragma unroll
        for (int j = 0; j < 2; j++) {
            int f = tid + j * 256;
            int r = f >> 3, kq = f & 7;
            int gr = rowg_s[r];
            float4 v4 = *reinterpret_cast<const float4*>(X + (size_t)gr * DIM + kb + kq * 4);
            *reinterpret_cast<float4*>(&Xs[r][kq * 4]) = v4;
        }
        // W tile: 64 words x 32 k, stored transposed (k-major) with swizzle
#pragma unroll
        for (int j = 0; j < 2; j++) {
            int f = tid + j * 256;
            int wr = f >> 3, kq = f & 7;
            int v = col0 + wr;
            float4 v4 = make_float4(0.0f, 0.0f, 0.0f, 0.0f);
            if (v < VWORDS)
                v4 = *reinterpret_cast<const float4*>(W + (size_t)v * DIM + kb + kq * 4);
            int cc = ((((wr >> 2) ^ kq) << 2) | (wr & 3));
            Ws[kq * 4 + 0][cc] = v4.x;
            Ws[kq * 4 + 1][cc] = v4.y;
            Ws[kq * 4 + 2][cc] = v4.z;
            Ws[kq * 4 + 3][cc] = v4.w;
        }
        __syncthreads();

#pragma unroll
        for (int k = 0; k < KC; k++) {
            float4 bv = *reinterpret_cast<const float4*>(&Ws[k][(tx ^ (k >> 2)) << 2]);
            float a0 = Xs[ty * 4 + 0][k];
            float a1 = Xs[ty * 4 + 1][k];
            float a2 = Xs[ty * 4 + 2][k];
            float a3 = Xs[ty * 4 + 3][k];
            acc[0][0] += a0 * bv.x; acc[0][1] += a0 * bv.y; acc[0][2] += a0 * bv.z; acc[0][3] += a0 * bv.w;
            acc[1][0] += a1 * bv.x; acc[1][1] += a1 * bv.y; acc[1][2] += a1 * bv.z; acc[1][3] += a1 * bv.w;
            acc[2][0] += a2 * bv.x; acc[2][1] += a2 * bv.y; acc[2][2] += a2 * bv.z; acc[2][3] += a2 * bv.w;
            acc[3][0] += a3 * bv.x; acc[3][1] += a3 * bv.y; acc[3][2] += a3 * bv.z; acc[3][3] += a3 * bv.w;
        }
        __syncthreads();
    }

    // Epilogue: compare and count
#pragma unroll
    for (int i = 0; i < 4; i++) {
        int r = ty * 4 + i;
        if (!vrow_s[r]) continue;
        float st = st_s[r];
        int t = tgt_s[r];
        int c = 0;
#pragma unroll
        for (int j = 0; j < 4; j++) {
            int v = col0 + tx * 4 + j;
            if (v >= VWORDS || v == t) continue;
            float s = w2s[tx * 4 + j] - 2.0f * acc[i][j];
            c += (s < st) || (s == st && v < t);
        }
        if (c) atomicAdd(&cnt_s[r], c);
    }
    __syncthreads();
    for (int i = tid; i < TM; i += 256) {
        if (vrow_s[i] && cnt_s[i]) atomicAdd(&g_counts[row0 + i], cnt_s[i]);
    }
}

// ---------------------------------------------------------------------------
// K4: finalize — acc = (#rows with rank < K) / nm
__global__ void k_final(float* __restrict__ out) {
    const int nm = g_nm;
    float s = 0.0f;
    for (int i = threadIdx.x; i < nm; i += 256)
        s += (g_counts[i] < KNN) ? 1.0f : 0.0f;
#pragma unroll
    for (int o = 16; o; o >>= 1) s += __shfl_down_sync(0xffffffffu, s, o);
    __shared__ float red[8];
    if ((threadIdx.x & 31) == 0) red[threadIdx.x >> 5] = s;
    __syncthreads();
    if (threadIdx.x == 0) {
        float tot = 0.0f;
#pragma unroll
        for (int i = 0; i < 8; i++) tot += red[i];
        out[0] = (nm > 0) ? (tot / (float)nm) : 0.0f;
    }
}

// ---------------------------------------------------------------------------
extern "C" void kernel_launch(void* const* d_in, const int* in_sizes, int n_in,
                              void* d_out, int out_size) {
    const float*     logits = (const float*)d_in[0];
    const long long* target = (const long long*)d_in[1];
    const int*       mask   = (const int*)d_in[2];
    const float*     W      = (const float*)d_in[3];

    k_zero<<<(N_ROWS + 255) / 256, 256>>>();
    k_w2<<<VWORDS, 128>>>(W);
    k_target<<<N_ROWS, 128>>>(logits, target, mask, W);
    dim3 grid(RTILES, VTILES);
    k_count<<<grid, 256>>>(logits, W);
    k_final<<<1, 256>>>((float*)d_out);
}